// round 1
// baseline (speedup 1.0000x reference)
#include <cuda_runtime.h>
#include <cstdint>

// Problem constants
#define Bc    4
#define Cc    256
#define Hc    56
#define Wc    56
#define Gc    16
#define Kc    7
#define TNUM  256
#define HW    (Hc * Wc)          // 3136
#define CG    (Cc / Gc)          // 16
#define KK    (Kc * Kc)          // 49
#define GK    (Gc * KK)          // 784
#define EPSc  1e-5f

// Scratch (no runtime allocation allowed)
__device__ float g_t[Bc * TNUM * HW];     // 12.8 MB
__device__ float g_ker[Bc * GK * HW];     // 39.3 MB

// ---------------------------------------------------------------------------
// SGEMM: C[batch][M,N] = A[M,K] * B[batch][K,N]  (A shared across batches)
// BM=BN=128, BK=8, TM=TN=8, 256 threads.
// EPI=1: BN(eval)+PReLU epilogue (kernel-generation "reduce" branch)
// EPI=2: +bias epilogue ("span" branch)
// ---------------------------------------------------------------------------
#define BM 128
#define BN 128
#define BKt 8
#define TM 8
#define TN 8

template <int EPI>
__global__ __launch_bounds__(256, 2)
void sgemm_kernel(const float* __restrict__ A,
                  const float* __restrict__ Bmat,
                  float* __restrict__ Cmat,
                  int M, int N, int Kd,
                  const float* __restrict__ bias,
                  const float* __restrict__ gamma,
                  const float* __restrict__ beta,
                  const float* __restrict__ mean,
                  const float* __restrict__ var,
                  const float* __restrict__ prelu_a)
{
    __shared__ float As[BKt][BM];
    __shared__ float Bs[BKt][BN];

    const int batch = blockIdx.z;
    const float* Bp = Bmat + (size_t)batch * Kd * N;
    float* Cp = Cmat + (size_t)batch * M * N;

    const int tid = threadIdx.x;
    const int tr = tid >> 4;          // 0..15
    const int tc = tid & 15;          // 0..15
    const int rowBase = blockIdx.x * BM;
    const int colBase = blockIdx.y * BN;

    float acc[TM][TN];
#pragma unroll
    for (int i = 0; i < TM; i++)
#pragma unroll
        for (int j = 0; j < TN; j++) acc[i][j] = 0.f;

    for (int kt = 0; kt < Kd; kt += BKt) {
        // Load A tile 128x8 (transposed into As[k][m]); 4 elems/thread
#pragma unroll
        for (int i = 0; i < 4; i++) {
            int idx = tid * 4 + i;
            int am = idx >> 3;
            int ak = idx & 7;
            int gm = rowBase + am;
            As[ak][am] = (gm < M) ? A[(size_t)gm * Kd + kt + ak] : 0.f;
        }
        // Load B tile 8x128; 4 consecutive elems/thread (float4 fast path)
        {
            int bk = tid >> 5;
            int bn = (tid & 31) * 4;
            int gn = colBase + bn;
            const float* bp = Bp + (size_t)(kt + bk) * N + gn;
            if (gn + 3 < N) {
                float4 v = *(const float4*)bp;
                Bs[bk][bn + 0] = v.x;
                Bs[bk][bn + 1] = v.y;
                Bs[bk][bn + 2] = v.z;
                Bs[bk][bn + 3] = v.w;
            } else {
#pragma unroll
                for (int i = 0; i < 4; i++)
                    Bs[bk][bn + i] = (gn + i < N) ? bp[i] : 0.f;
            }
        }
        __syncthreads();

#pragma unroll
        for (int kk = 0; kk < BKt; kk++) {
            float ra[TM], rb[TN];
#pragma unroll
            for (int i = 0; i < TM; i++) ra[i] = As[kk][tr * TM + i];
#pragma unroll
            for (int j = 0; j < TN; j++) rb[j] = Bs[kk][tc * TN + j];
#pragma unroll
            for (int i = 0; i < TM; i++)
#pragma unroll
                for (int j = 0; j < TN; j++) acc[i][j] += ra[i] * rb[j];
        }
        __syncthreads();
    }

    // Epilogue + store
#pragma unroll
    for (int i = 0; i < TM; i++) {
        int gm = rowBase + tr * TM + i;
        if (gm >= M) continue;
        float bb = bias[gm];
        float sc = 0.f, mn = 0.f, bt = 0.f, aa = 0.f;
        if (EPI == 1) {
            sc = gamma[gm] * rsqrtf(var[gm] + EPSc);
            mn = mean[gm];
            bt = beta[gm];
            aa = prelu_a[0];
        }
#pragma unroll
        for (int j = 0; j < TN; j++) {
            int gn = colBase + tc * TN + j;
            if (gn >= N) continue;
            float v = acc[i][j] + bb;
            if (EPI == 1) {
                v = (v - mn) * sc + bt;
                v = v > 0.f ? v : aa * v;   // PReLU
            }
            Cp[(size_t)gm * N + gn] = v;
        }
    }
}

// ---------------------------------------------------------------------------
// Involution aggregation:
// out[b,c,h,w] = sum_{i,j in 7x7} xpad[b,c,h+i-3,w+j-3] * ker[b, (c/16)*49 + i*7+j, h, w]
// Block = (row-tile of 4 rows, group g, batch b). 256 threads.
// Each thread owns one pixel; its 49 ker taps live in registers and are
// reused across the 16 channels of the group. x halo staged in smem per chan.
// ---------------------------------------------------------------------------
#define TH 4     // rows per block (56 % 4 == 0)

__global__ __launch_bounds__(256)
void involution_kernel(const float* __restrict__ x,
                       const float* __restrict__ ker,
                       float* __restrict__ out)
{
    __shared__ float xs[TH + 6][64];   // 62 used cols, 64 stride

    const int tileRow = blockIdx.x;    // 0..13
    const int g = blockIdx.y;          // 0..15
    const int b = blockIdx.z;          // 0..3
    const int tid = threadIdx.x;

    const int h0 = tileRow * TH;
    const bool active = tid < TH * Wc; // 224 active threads
    const int r  = tid / Wc;           // local row 0..3
    const int cw = tid % Wc;           // col 0..55
    const int h  = h0 + r;

    // ker taps for this pixel -> registers (coalesced along w)
    float kreg[KK];
    if (active) {
        const float* kp = ker + (((size_t)b * GK + g * KK) * HW) + h * Wc + cw;
#pragma unroll
        for (int idx = 0; idx < KK; idx++) kreg[idx] = kp[(size_t)idx * HW];
    }

    for (int ci = 0; ci < CG; ci++) {
        const int c = g * CG + ci;
        const float* xc = x + ((size_t)(b * Cc + c)) * HW;

        // cooperative halo load: rows h0-3 .. h0+TH+2, cols -3..58
        for (int i = tid; i < (TH + 6) * 62; i += 256) {
            int rr = i / 62;
            int cc = i % 62;
            int gh = h0 - 3 + rr;
            int gw = cc - 3;
            float v = 0.f;
            if (gh >= 0 && gh < Hc && gw >= 0 && gw < Wc)
                v = xc[gh * Wc + gw];
            xs[rr][cc] = v;
        }
        __syncthreads();

        if (active) {
            float acc = 0.f;
#pragma unroll
            for (int i = 0; i < Kc; i++)
#pragma unroll
                for (int j = 0; j < Kc; j++)
                    acc += xs[r + i][cw + j] * kreg[i * Kc + j];
            out[((size_t)(b * Cc + c) * Hc + h) * Wc + cw] = acc;
        }
        __syncthreads();
    }
}

// ---------------------------------------------------------------------------
// Launch
// Inputs (metadata order):
// 0 x[B,C,H,W] 1 reduce_w[TNUM,C] 2 reduce_b[TNUM] 3 bn_gamma 4 bn_beta
// 5 bn_mean 6 bn_var 7 prelu_a[1] 8 span_w[GK,TNUM] 9 span_b[GK]
// ---------------------------------------------------------------------------
extern "C" void kernel_launch(void* const* d_in, const int* in_sizes, int n_in,
                              void* d_out, int out_size)
{
    const float* x        = (const float*)d_in[0];
    const float* reduce_w = (const float*)d_in[1];
    const float* reduce_b = (const float*)d_in[2];
    const float* bn_gamma = (const float*)d_in[3];
    const float* bn_beta  = (const float*)d_in[4];
    const float* bn_mean  = (const float*)d_in[5];
    const float* bn_var   = (const float*)d_in[6];
    const float* prelu_a  = (const float*)d_in[7];
    const float* span_w   = (const float*)d_in[8];
    const float* span_b   = (const float*)d_in[9];
    float* out = (float*)d_out;

    float* t_buf;
    float* ker_buf;
    cudaGetSymbolAddress((void**)&t_buf, g_t);
    cudaGetSymbolAddress((void**)&ker_buf, g_ker);

    // GEMM1: T = BN_PReLU(reduce_w @ X)   M=256, N=3136, K=256, batched x4
    {
        dim3 grid((TNUM + BM - 1) / BM, (HW + BN - 1) / BN, Bc);
        sgemm_kernel<1><<<grid, 256>>>(reduce_w, x, t_buf,
                                       TNUM, HW, Cc,
                                       reduce_b, bn_gamma, bn_beta,
                                       bn_mean, bn_var, prelu_a);
    }
    // GEMM2: KER = span_w @ T + span_b    M=784, N=3136, K=256, batched x4
    {
        dim3 grid((GK + BM - 1) / BM, (HW + BN - 1) / BN, Bc);
        sgemm_kernel<2><<<grid, 256>>>(span_w, t_buf, ker_buf,
                                       GK, HW, TNUM,
                                       span_b, nullptr, nullptr,
                                       nullptr, nullptr, nullptr);
    }
    // Involution aggregation
    {
        dim3 grid(Hc / TH, Gc, Bc);
        involution_kernel<<<grid, 256>>>(x, ker_buf, out);
    }
}

// round 3
// speedup vs baseline: 1.8971x; 1.8971x over previous
#include <cuda_runtime.h>
#include <cuda_fp16.h>
#include <cstdint>

// ---------------------------------------------------------------------------
// Problem constants
// ---------------------------------------------------------------------------
#define Bc    4
#define Cc    256
#define Hc    56
#define Wc    56
#define Gc    16
#define Kc    7
#define TNUM  256
#define HW    (Hc * Wc)          // 3136
#define CG    (Cc / Gc)          // 16
#define KK    (Kc * Kc)          // 49
#define GK    (Gc * KK)          // 784
#define EPSc  1e-5f
#define KDIM  256

// Scratch (no runtime allocation allowed)
__device__ float g_t  [Bc * TNUM * HW];   // T   [b][t][hw]   12.8 MB
__device__ float g_ker[Bc * GK * HW];     // KER [b][gk][hw]  39.3 MB

// ---------------------------------------------------------------------------
// HMMA GEMM via mma.sync (sm_80 ISA — no arch feature bits needed)
//   D[M,N] = A[M,K] * B[K,N],  K = 256.
//   fp32 operands split into fp16 hi+lo; 3 MMAs (hh, hl, lh) per k-step
//   => ~1e-6 relative accuracy, 3x fp16 MMA work.
// BM=BN=128, BK=32, 256 threads, warp grid 4(M) x 2(N), warp tile 32x64.
// EPI=1: BN(eval)+PReLU epilogue. EPI=2: +bias epilogue.
// ---------------------------------------------------------------------------
#define BMg 128
#define BNg 128
#define BKg 32
#define PKH 36                   // smem pitch in halves (72B rows: <=2-way conflicts)
#define NCH (KDIM / BKg)         // 8

#define MMA16816(Cr, A0, A1, A2, A3, B0, B1)                              \
    asm volatile(                                                          \
        "mma.sync.aligned.m16n8k16.row.col.f32.f16.f16.f32 "              \
        "{%0,%1,%2,%3}, {%4,%5,%6,%7}, {%8,%9}, {%0,%1,%2,%3};"           \
        : "+f"((Cr)[0]), "+f"((Cr)[1]), "+f"((Cr)[2]), "+f"((Cr)[3])       \
        : "r"(A0), "r"(A1), "r"(A2), "r"(A3), "r"(B0), "r"(B1))

// split two floats into packed-half2 hi and lo words
__device__ __forceinline__ void split2(float x, float y,
                                       uint32_t& hi, uint32_t& lo) {
    __half hx = __float2half_rn(x);
    __half hy = __float2half_rn(y);
    __half lx = __float2half_rn(x - __half2float(hx));
    __half ly = __float2half_rn(y - __half2float(hy));
    hi = (uint32_t)__half_as_ushort(hx) | ((uint32_t)__half_as_ushort(hy) << 16);
    lo = (uint32_t)__half_as_ushort(lx) | ((uint32_t)__half_as_ushort(ly) << 16);
}

template <int EPI>
__global__ __launch_bounds__(256)
void gemm_mma_kernel(const float* __restrict__ A,      // [M,K] K-major
                     const float* __restrict__ Bmat,   // [batch][K,Nfull]
                     float* __restrict__ Cmat,         // [batch][M,Nfull]
                     int M, int Nfull,
                     const float* __restrict__ bias,
                     const float* __restrict__ gamma,
                     const float* __restrict__ beta,
                     const float* __restrict__ mean,
                     const float* __restrict__ var,
                     const float* __restrict__ prelu_a)
{
    __shared__ __align__(16) uint16_t sA_hi[BMg * PKH];
    __shared__ __align__(16) uint16_t sA_lo[BMg * PKH];
    __shared__ __align__(16) uint16_t sB_hi[BNg * PKH];
    __shared__ __align__(16) uint16_t sB_lo[BNg * PKH];

    const int tid  = threadIdx.x;
    const int lane = tid & 31;
    const int wid  = tid >> 5;
    const int wm   = wid & 3;          // 0..3 : 32-row M sub-tile
    const int wn   = wid >> 2;         // 0..1 : 64-col N sub-tile
    const int g    = lane >> 2;        // 0..7
    const int t2   = (lane & 3) * 2;   // 0,2,4,6

    const int rowBase = blockIdx.x * BMg;
    const int colBase = blockIdx.y * BNg;
    const int batch   = blockIdx.z;
    const float* Bp = Bmat + (size_t)batch * KDIM * Nfull;

    float acc[2][8][4];
#pragma unroll
    for (int mt = 0; mt < 2; mt++)
#pragma unroll
        for (int nt = 0; nt < 8; nt++)
#pragma unroll
            for (int i = 0; i < 4; i++) acc[mt][nt][i] = 0.f;

    // staging registers for the global->smem pipeline
    float4 av[4], bv[4];

    const int a_row[4] = { (0 * 256 + tid) >> 3, (1 * 256 + tid) >> 3,
                           (2 * 256 + tid) >> 3, (3 * 256 + tid) >> 3 };
    const int a_q = tid & 7;                 // same for all i since 256 % 8 == 0
    const int b_q  = tid & 31;               // n-float4 index
    const int b_kb = (tid >> 5) * 4;         // 4 k-rows per warp

    auto loadA = [&](int ch) {
        const int kc = ch * BKg;
#pragma unroll
        for (int i = 0; i < 4; i++) {
            int gm = rowBase + a_row[i];
            av[i] = (gm < M)
                ? *(const float4*)(A + (size_t)gm * KDIM + kc + a_q * 4)
                : make_float4(0.f, 0.f, 0.f, 0.f);
        }
    };
    auto loadB = [&](int ch) {
        const int kc = ch * BKg;
        const int col = colBase + b_q * 4;
        const bool ok = col < Nfull;          // Nfull % 4 == 0 => float4-safe
#pragma unroll
        for (int i = 0; i < 4; i++) {
            bv[i] = ok
                ? *(const float4*)(Bp + (size_t)(kc + b_kb + i) * Nfull + col)
                : make_float4(0.f, 0.f, 0.f, 0.f);
        }
    };
    auto stage = [&]() {
        // A: [m][k] rows, pairs along k
#pragma unroll
        for (int i = 0; i < 4; i++) {
            uint32_t h0, l0, h1, l1;
            split2(av[i].x, av[i].y, h0, l0);
            split2(av[i].z, av[i].w, h1, l1);
            int addr = a_row[i] * PKH + a_q * 4;
            *(uint2*)&sA_hi[addr] = make_uint2(h0, h1);
            *(uint2*)&sA_lo[addr] = make_uint2(l0, l1);
        }
        // B: transpose to [n][k], pairs along k
        const float* f0 = (const float*)&bv[0];
        const float* f1 = (const float*)&bv[1];
        const float* f2 = (const float*)&bv[2];
        const float* f3 = (const float*)&bv[3];
#pragma unroll
        for (int n_off = 0; n_off < 4; n_off++) {
            uint32_t h0, l0, h1, l1;
            split2(f0[n_off], f1[n_off], h0, l0);
            split2(f2[n_off], f3[n_off], h1, l1);
            int addr = (b_q * 4 + n_off) * PKH + b_kb;
            *(uint2*)&sB_hi[addr] = make_uint2(h0, h1);
            *(uint2*)&sB_lo[addr] = make_uint2(l0, l1);
        }
    };

    loadA(0); loadB(0);

    for (int c = 0; c < NCH; c++) {
        if (c) __syncthreads();               // previous compute done
        stage();
        __syncthreads();
        if (c + 1 < NCH) { loadA(c + 1); loadB(c + 1); }  // overlap w/ compute

#pragma unroll
        for (int ks = 0; ks < 2; ks++) {      // two k16 steps per chunk
            const int k0 = ks * 16 + t2;
            uint32_t ah[2][4], al[2][4];
#pragma unroll
            for (int mt = 0; mt < 2; mt++) {
                int mr = wm * 32 + mt * 16 + g;
                ah[mt][0] = *(const uint32_t*)&sA_hi[(mr    ) * PKH + k0    ];
                ah[mt][1] = *(const uint32_t*)&sA_hi[(mr + 8) * PKH + k0    ];
                ah[mt][2] = *(const uint32_t*)&sA_hi[(mr    ) * PKH + k0 + 8];
                ah[mt][3] = *(const uint32_t*)&sA_hi[(mr + 8) * PKH + k0 + 8];
                al[mt][0] = *(const uint32_t*)&sA_lo[(mr    ) * PKH + k0    ];
                al[mt][1] = *(const uint32_t*)&sA_lo[(mr + 8) * PKH + k0    ];
                al[mt][2] = *(const uint32_t*)&sA_lo[(mr    ) * PKH + k0 + 8];
                al[mt][3] = *(const uint32_t*)&sA_lo[(mr + 8) * PKH + k0 + 8];
            }
#pragma unroll
            for (int nt = 0; nt < 8; nt++) {
                int n = wn * 64 + nt * 8 + g;
                uint32_t bh0 = *(const uint32_t*)&sB_hi[n * PKH + k0    ];
                uint32_t bh1 = *(const uint32_t*)&sB_hi[n * PKH + k0 + 8];
                uint32_t bl0 = *(const uint32_t*)&sB_lo[n * PKH + k0    ];
                uint32_t bl1 = *(const uint32_t*)&sB_lo[n * PKH + k0 + 8];
#pragma unroll
                for (int mt = 0; mt < 2; mt++) {
                    MMA16816(acc[mt][nt], ah[mt][0], ah[mt][1], ah[mt][2], ah[mt][3], bh0, bh1);
                    MMA16816(acc[mt][nt], ah[mt][0], ah[mt][1], ah[mt][2], ah[mt][3], bl0, bl1);
                    MMA16816(acc[mt][nt], al[mt][0], al[mt][1], al[mt][2], al[mt][3], bh0, bh1);
                }
            }
        }
    }

    // ---- epilogue ----
    float* Cb = Cmat + (size_t)batch * M * Nfull;
#pragma unroll
    for (int mt = 0; mt < 2; mt++) {
        int r0 = rowBase + wm * 32 + mt * 16 + g;
        int r1 = r0 + 8;
#pragma unroll
        for (int half_ = 0; half_ < 2; half_++) {
            int rr = half_ ? r1 : r0;
            if (rr >= M) continue;
            float bb = bias[rr];
            float sc = 0.f, mn = 0.f, bt = 0.f, aa = 0.f;
            if (EPI == 1) {
                sc = gamma[rr] * rsqrtf(var[rr] + EPSc);
                mn = mean[rr];
                bt = beta[rr];
                aa = prelu_a[0];
            }
            float* Crow = Cb + (size_t)rr * Nfull;
#pragma unroll
            for (int nt = 0; nt < 8; nt++) {
                int col = colBase + wn * 64 + nt * 8 + t2;
                if (col >= Nfull) continue;   // Nfull even, col even => col+1 ok
                float v0 = acc[mt][nt][half_ * 2 + 0] + bb;
                float v1 = acc[mt][nt][half_ * 2 + 1] + bb;
                if (EPI == 1) {
                    v0 = (v0 - mn) * sc + bt;
                    v1 = (v1 - mn) * sc + bt;
                    v0 = v0 > 0.f ? v0 : aa * v0;
                    v1 = v1 > 0.f ? v1 : aa * v1;
                }
                *(float2*)(Crow + col) = make_float2(v0, v1);
            }
        }
    }
}

// ---------------------------------------------------------------------------
// Involution aggregation (unchanged from passing baseline)
// ---------------------------------------------------------------------------
#define TH 4

__global__ __launch_bounds__(256)
void involution_kernel(const float* __restrict__ x,
                       const float* __restrict__ ker,
                       float* __restrict__ out)
{
    __shared__ float xs[TH + 6][64];

    const int tileRow = blockIdx.x;
    const int g = blockIdx.y;
    const int b = blockIdx.z;
    const int tid = threadIdx.x;

    const int h0 = tileRow * TH;
    const bool active = tid < TH * Wc;
    const int r  = tid / Wc;
    const int cw = tid % Wc;
    const int h  = h0 + r;

    float kreg[KK];
    if (active) {
        const float* kp = ker + (((size_t)b * GK + g * KK) * HW) + h * Wc + cw;
#pragma unroll
        for (int idx = 0; idx < KK; idx++) kreg[idx] = kp[(size_t)idx * HW];
    }

    for (int ci = 0; ci < CG; ci++) {
        const int c = g * CG + ci;
        const float* xc = x + ((size_t)(b * Cc + c)) * HW;
        for (int i = tid; i < (TH + 6) * 62; i += 256) {
            int rr = i / 62;
            int cc = i % 62;
            int gh = h0 - 3 + rr;
            int gw = cc - 3;
            float v = 0.f;
            if (gh >= 0 && gh < Hc && gw >= 0 && gw < Wc)
                v = xc[gh * Wc + gw];
            xs[rr][cc] = v;
        }
        __syncthreads();
        if (active) {
            float a = 0.f;
#pragma unroll
            for (int i = 0; i < Kc; i++)
#pragma unroll
                for (int j = 0; j < Kc; j++)
                    a += xs[r + i][cw + j] * kreg[i * Kc + j];
            out[((size_t)(b * Cc + c) * Hc + h) * Wc + cw] = a;
        }
        __syncthreads();
    }
}

// ---------------------------------------------------------------------------
// Launch
// ---------------------------------------------------------------------------
extern "C" void kernel_launch(void* const* d_in, const int* in_sizes, int n_in,
                              void* d_out, int out_size)
{
    const float* x        = (const float*)d_in[0];
    const float* reduce_w = (const float*)d_in[1];
    const float* reduce_b = (const float*)d_in[2];
    const float* bn_gamma = (const float*)d_in[3];
    const float* bn_beta  = (const float*)d_in[4];
    const float* bn_mean  = (const float*)d_in[5];
    const float* bn_var   = (const float*)d_in[6];
    const float* prelu_a  = (const float*)d_in[7];
    const float* span_w   = (const float*)d_in[8];
    const float* span_b   = (const float*)d_in[9];
    float* out = (float*)d_out;

    float *t_buf, *ker_buf;
    cudaGetSymbolAddress((void**)&t_buf, g_t);
    cudaGetSymbolAddress((void**)&ker_buf, g_ker);

    // GEMM1: T = BN_PReLU(reduce_w @ x)   M=256, N=3136, K=256, batched x4
    {
        dim3 grid((TNUM + BMg - 1) / BMg, (HW + BNg - 1) / BNg, Bc);
        gemm_mma_kernel<1><<<grid, 256>>>(reduce_w, x, t_buf,
                                          TNUM, HW,
                                          reduce_b, bn_gamma, bn_beta,
                                          bn_mean, bn_var, prelu_a);
    }
    // GEMM2: KER = span_w @ T + span_b    M=784, N=3136, K=256, batched x4
    {
        dim3 grid((GK + BMg - 1) / BMg, (HW + BNg - 1) / BNg, Bc);
        gemm_mma_kernel<2><<<grid, 256>>>(span_w, t_buf, ker_buf,
                                          GK, HW,
                                          span_b, nullptr, nullptr,
                                          nullptr, nullptr, nullptr);
    }
    // Involution aggregation
    {
        dim3 grid(Hc / TH, Gc, Bc);
        involution_kernel<<<grid, 256>>>(x, ker_buf, out);
    }
}

// round 4
// speedup vs baseline: 2.2164x; 1.1683x over previous
#include <cuda_runtime.h>
#include <cuda_fp16.h>
#include <cstdint>

// ---------------------------------------------------------------------------
// Problem constants
// ---------------------------------------------------------------------------
#define Bc    4
#define Cc    256
#define Hc    56
#define Wc    56
#define Gc    16
#define Kc    7
#define TNUM  256
#define HW    (Hc * Wc)          // 3136
#define CG    (Cc / Gc)          // 16
#define KK    (Kc * Kc)          // 49
#define GK    (Gc * KK)          // 784
#define EPSc  1e-5f
#define KDIM  256

// ---------------------------------------------------------------------------
// Scratch (no runtime allocation allowed)
// ---------------------------------------------------------------------------
__device__ __half g_xh[Bc * Cc * HW];     // x split hi   6.4 MB
__device__ __half g_xl[Bc * Cc * HW];     // x split lo   6.4 MB
__device__ __half g_th[Bc * TNUM * HW];   // T split hi   6.4 MB
__device__ __half g_tl[Bc * TNUM * HW];   // T split lo   6.4 MB
__device__ __half g_w1h[TNUM * Cc];
__device__ __half g_w1l[TNUM * Cc];
__device__ __half g_w2h[GK * KDIM];
__device__ __half g_w2l[GK * KDIM];
__device__ float  g_ker[Bc * GK * HW];    // KER 39.3 MB

// ---------------------------------------------------------------------------
// helpers
// ---------------------------------------------------------------------------
__device__ __forceinline__ void split2(float x, float y,
                                       uint32_t& hi, uint32_t& lo) {
    __half hx = __float2half_rn(x);
    __half hy = __float2half_rn(y);
    __half lx = __float2half_rn(x - __half2float(hx));
    __half ly = __float2half_rn(y - __half2float(hy));
    hi = (uint32_t)__half_as_ushort(hx) | ((uint32_t)__half_as_ushort(hy) << 16);
    lo = (uint32_t)__half_as_ushort(lx) | ((uint32_t)__half_as_ushort(ly) << 16);
}

__device__ __forceinline__ uint32_t smem_u32(const void* p) {
    uint32_t a;
    asm("{ .reg .u64 t; cvta.to.shared.u64 t, %1; cvt.u32.u64 %0, t; }"
        : "=r"(a) : "l"(p));
    return a;
}

#define MMA16816(Cr, Ar, B0, B1)                                           \
    asm volatile(                                                          \
        "mma.sync.aligned.m16n8k16.row.col.f32.f16.f16.f32 "              \
        "{%0,%1,%2,%3}, {%4,%5,%6,%7}, {%8,%9}, {%0,%1,%2,%3};"           \
        : "+f"((Cr)[0]), "+f"((Cr)[1]), "+f"((Cr)[2]), "+f"((Cr)[3])       \
        : "r"((Ar)[0]), "r"((Ar)[1]), "r"((Ar)[2]), "r"((Ar)[3]),          \
          "r"(B0), "r"(B1))

#define LDSM4(R, addr)                                                     \
    asm volatile("ldmatrix.sync.aligned.m8n8.x4.shared.b16 "               \
        "{%0,%1,%2,%3}, [%4];"                                             \
        : "=r"((R)[0]), "=r"((R)[1]), "=r"((R)[2]), "=r"((R)[3])           \
        : "r"(addr))

#define LDSM4T(R, addr)                                                    \
    asm volatile("ldmatrix.sync.aligned.m8n8.x4.trans.shared.b16 "         \
        "{%0,%1,%2,%3}, [%4];"                                             \
        : "=r"((R)[0]), "=r"((R)[1]), "=r"((R)[2]), "=r"((R)[3])           \
        : "r"(addr))

#define CP_ASYNC16(dst, src, sz)                                           \
    asm volatile("cp.async.cg.shared.global [%0], [%1], 16, %2;"           \
        :: "r"(dst), "l"(src), "r"(sz))
#define CP_COMMIT() asm volatile("cp.async.commit_group;")

// ---------------------------------------------------------------------------
// fp32 -> fp16 hi/lo split (elementwise, float4-vectorized)
// ---------------------------------------------------------------------------
__global__ __launch_bounds__(256)
void split_kernel(const float4* __restrict__ src,
                  uint2* __restrict__ hi, uint2* __restrict__ lo, int n4)
{
    int i = blockIdx.x * blockDim.x + threadIdx.x;
    if (i >= n4) return;
    float4 v = src[i];
    uint32_t h0, l0, h1, l1;
    split2(v.x, v.y, h0, l0);
    split2(v.z, v.w, h1, l1);
    hi[i] = make_uint2(h0, h1);
    lo[i] = make_uint2(l0, l1);
}

// ---------------------------------------------------------------------------
// Split-fp16 HMMA GEMM, cp.async + ldmatrix pipeline.
//   D[M,N] = A[M,K]*B[K,N], K=256. A,B pre-split into fp16 hi/lo arrays.
//   3 MMAs per k-step (hh + hl + lh) => ~1e-6 relative accuracy.
// Block: 512 thr (16 warps, 4x4), tile 128x128, BK=32, 3-stage cp.async ring.
// EPI=1: BN+PReLU, output split to half hi/lo (feeds GEMM2).
// EPI=2: +bias, fp32 output.
// ---------------------------------------------------------------------------
#define BMg 128
#define BNg 128
#define BKg 32
#define NCH (KDIM / BKg)          // 8
#define NST 3
#define PKA 40                    // A smem pitch (halves)
#define PKB 136                   // B smem pitch (halves)
#define A_BY (BMg * PKA * 2)      // 10240 B per array
#define B_BY (BKg * PKB * 2)      // 8704 B per array
#define STG_BY (2 * A_BY + 2 * B_BY)   // 37888
#define SMEM_TOT (NST * STG_BY)        // 113664

template <int EPI>
__global__ __launch_bounds__(512, 1)
void gemm_split_kernel(const __half* __restrict__ Ahi,  // [M][K]
                       const __half* __restrict__ Alo,
                       const __half* __restrict__ Bhi,  // [batch][K][N]
                       const __half* __restrict__ Blo,
                       float* __restrict__ Cf,          // EPI=2 output
                       __half* __restrict__ Chi,        // EPI=1 outputs
                       __half* __restrict__ Clo,
                       int M, int Nfull,
                       const float* __restrict__ bias,
                       const float* __restrict__ gamma,
                       const float* __restrict__ beta,
                       const float* __restrict__ mean,
                       const float* __restrict__ var,
                       const float* __restrict__ prelu_a)
{
    extern __shared__ __align__(16) char smem[];
    const uint32_t sbase = smem_u32(smem);

    const int tid  = threadIdx.x;
    const int lane = tid & 31;
    const int wid  = tid >> 5;
    const int wm   = wid & 3;           // M warp 0..3
    const int wn   = wid >> 2;          // N warp 0..3
    const int lane15 = lane & 15;
    const int hi8    = (lane & 16) >> 1; // 0 or 8
    const int g    = lane >> 2;
    const int t2   = (lane & 3) * 2;

    const int rowBase = blockIdx.x * BMg;
    const int colBase = blockIdx.y * BNg;
    const int batch   = blockIdx.z;
    const __half* BhiP = Bhi + (size_t)batch * KDIM * Nfull;
    const __half* BloP = Blo + (size_t)batch * KDIM * Nfull;

    // cp.async source/dest indices (fixed per thread)
    const int a_row = tid >> 2;          // 0..127
    const int a_kq  = tid & 3;           // 16B chunk along k
    const int b_kr  = tid >> 4;          // 0..31
    const int b_nq  = tid & 15;          // 16B chunk along n

    const int gmA   = rowBase + a_row;
    const uint32_t aSz = (gmA < M) ? 16u : 0u;
    const int gmAc  = (gmA < M) ? gmA : 0;
    const int n0    = colBase + b_nq * 8;
    const uint32_t bSz = (n0 + 8 <= Nfull) ? 16u : 0u;
    const int n0c   = (n0 + 8 <= Nfull) ? n0 : 0;

    auto issue = [&](int ch, int s) {
        const int kc = ch * BKg;
        const uint32_t stg = sbase + s * STG_BY;
        // A hi / lo
        const uint32_t adst = stg + a_row * (PKA * 2) + a_kq * 16;
        const size_t  asrc = (size_t)gmAc * KDIM + kc + a_kq * 8;
        CP_ASYNC16(adst,            Ahi + asrc, aSz);
        CP_ASYNC16(adst + A_BY,     Alo + asrc, aSz);
        // B hi / lo
        const uint32_t bdst = stg + 2 * A_BY + b_kr * (PKB * 2) + b_nq * 16;
        const size_t  bsrc = (size_t)(kc + b_kr) * Nfull + n0c;
        CP_ASYNC16(bdst,            BhiP + bsrc, bSz);
        CP_ASYNC16(bdst + B_BY,     BloP + bsrc, bSz);
        CP_COMMIT();
    };

    float acc[2][4][4];
#pragma unroll
    for (int mt = 0; mt < 2; mt++)
#pragma unroll
        for (int nt = 0; nt < 4; nt++)
#pragma unroll
            for (int i = 0; i < 4; i++) acc[mt][nt][i] = 0.f;

    // prologue: 3 stages in flight
    issue(0, 0); issue(1, 1); issue(2, 2);

    for (int c = 0; c < NCH; c++) {
        if (c <= NCH - 3)      asm volatile("cp.async.wait_group 2;");
        else if (c == NCH - 2) asm volatile("cp.async.wait_group 1;");
        else                   asm volatile("cp.async.wait_group 0;");
        __syncthreads();

        const int s = c % NST;
        const uint32_t aHiB = sbase + s * STG_BY;
        const uint32_t aLoB = aHiB + A_BY;
        const uint32_t bHiB = aHiB + 2 * A_BY;
        const uint32_t bLoB = bHiB + B_BY;

#pragma unroll
        for (int ks = 0; ks < 2; ks++) {
            const int k0 = ks * 16;
            uint32_t ah[2][4], al[2][4], bh[2][4], bl[2][4];
#pragma unroll
            for (int mt = 0; mt < 2; mt++) {
                int row = wm * 32 + mt * 16 + lane15;
                uint32_t off = row * (PKA * 2) + (k0 + hi8) * 2;
                LDSM4(ah[mt], aHiB + off);
                LDSM4(al[mt], aLoB + off);
            }
#pragma unroll
            for (int nb = 0; nb < 2; nb++) {
                int nn   = wn * 32 + nb * 16 + hi8;
                int krow = k0 + lane15;
                uint32_t off = krow * (PKB * 2) + nn * 2;
                LDSM4T(bh[nb], bHiB + off);
                LDSM4T(bl[nb], bLoB + off);
            }
#pragma unroll
            for (int nb = 0; nb < 2; nb++)
#pragma unroll
                for (int ng = 0; ng < 2; ng++) {
                    uint32_t b0h = bh[nb][2 * ng], b1h = bh[nb][2 * ng + 1];
                    uint32_t b0l = bl[nb][2 * ng], b1l = bl[nb][2 * ng + 1];
#pragma unroll
                    for (int mt = 0; mt < 2; mt++) {
                        float* C = acc[mt][nb * 2 + ng];
                        MMA16816(C, ah[mt], b0h, b1h);   // hi*hi
                        MMA16816(C, ah[mt], b0l, b1l);   // hi*lo
                        MMA16816(C, al[mt], b0h, b1h);   // lo*hi
                    }
                }
        }
        __syncthreads();
        if (c + 3 < NCH) issue(c + 3, (c + 3) % NST);
    }

    // ---- epilogue ----
#pragma unroll
    for (int mt = 0; mt < 2; mt++) {
        int r0 = rowBase + wm * 32 + mt * 16 + g;
#pragma unroll
        for (int half_ = 0; half_ < 2; half_++) {
            int rr = r0 + half_ * 8;
            if (rr >= M) continue;
            float bb = bias[rr];
            float sc = 0.f, mn = 0.f, bt = 0.f, aa = 0.f;
            if (EPI == 1) {
                sc = gamma[rr] * rsqrtf(var[rr] + EPSc);
                mn = mean[rr];
                bt = beta[rr];
                aa = prelu_a[0];
            }
#pragma unroll
            for (int nt = 0; nt < 4; nt++) {
                int col = colBase + wn * 32 + nt * 8 + t2;
                if (col >= Nfull) continue;
                float v0 = acc[mt][nt][half_ * 2 + 0] + bb;
                float v1 = acc[mt][nt][half_ * 2 + 1] + bb;
                if (EPI == 1) {
                    v0 = (v0 - mn) * sc + bt;
                    v1 = (v1 - mn) * sc + bt;
                    v0 = v0 > 0.f ? v0 : aa * v0;
                    v1 = v1 > 0.f ? v1 : aa * v1;
                    uint32_t hw_, lw_;
                    split2(v0, v1, hw_, lw_);
                    size_t idx = ((size_t)batch * M + rr) * Nfull + col;
                    *(uint32_t*)(Chi + idx) = hw_;
                    *(uint32_t*)(Clo + idx) = lw_;
                } else {
                    size_t idx = ((size_t)batch * M + rr) * Nfull + col;
                    *(float2*)(Cf + idx) = make_float2(v0, v1);
                }
            }
        }
    }
}

// ---------------------------------------------------------------------------
// Involution aggregation (unchanged)
// ---------------------------------------------------------------------------
#define TH 4

__global__ __launch_bounds__(256)
void involution_kernel(const float* __restrict__ x,
                       const float* __restrict__ ker,
                       float* __restrict__ out)
{
    __shared__ float xs[TH + 6][64];

    const int tileRow = blockIdx.x;
    const int g = blockIdx.y;
    const int b = blockIdx.z;
    const int tid = threadIdx.x;

    const int h0 = tileRow * TH;
    const bool active = tid < TH * Wc;
    const int r  = tid / Wc;
    const int cw = tid % Wc;
    const int h  = h0 + r;

    float kreg[KK];
    if (active) {
        const float* kp = ker + (((size_t)b * GK + g * KK) * HW) + h * Wc + cw;
#pragma unroll
        for (int idx = 0; idx < KK; idx++) kreg[idx] = kp[(size_t)idx * HW];
    }

    for (int ci = 0; ci < CG; ci++) {
        const int c = g * CG + ci;
        const float* xc = x + ((size_t)(b * Cc + c)) * HW;
        for (int i = tid; i < (TH + 6) * 62; i += 256) {
            int rr = i / 62;
            int cc = i % 62;
            int gh = h0 - 3 + rr;
            int gw = cc - 3;
            float v = 0.f;
            if (gh >= 0 && gh < Hc && gw >= 0 && gw < Wc)
                v = xc[gh * Wc + gw];
            xs[rr][cc] = v;
        }
        __syncthreads();
        if (active) {
            float a = 0.f;
#pragma unroll
            for (int i = 0; i < Kc; i++)
#pragma unroll
                for (int j = 0; j < Kc; j++)
                    a += xs[r + i][cw + j] * kreg[i * Kc + j];
            out[((size_t)(b * Cc + c) * Hc + h) * Wc + cw] = a;
        }
        __syncthreads();
    }
}

// ---------------------------------------------------------------------------
// Launch
// ---------------------------------------------------------------------------
extern "C" void kernel_launch(void* const* d_in, const int* in_sizes, int n_in,
                              void* d_out, int out_size)
{
    const float* x        = (const float*)d_in[0];
    const float* reduce_w = (const float*)d_in[1];
    const float* reduce_b = (const float*)d_in[2];
    const float* bn_gamma = (const float*)d_in[3];
    const float* bn_beta  = (const float*)d_in[4];
    const float* bn_mean  = (const float*)d_in[5];
    const float* bn_var   = (const float*)d_in[6];
    const float* prelu_a  = (const float*)d_in[7];
    const float* span_w   = (const float*)d_in[8];
    const float* span_b   = (const float*)d_in[9];
    float* out = (float*)d_out;

    __half *xh, *xl, *th, *tl, *w1h, *w1l, *w2h, *w2l;
    float* ker_buf;
    cudaGetSymbolAddress((void**)&xh, g_xh);
    cudaGetSymbolAddress((void**)&xl, g_xl);
    cudaGetSymbolAddress((void**)&th, g_th);
    cudaGetSymbolAddress((void**)&tl, g_tl);
    cudaGetSymbolAddress((void**)&w1h, g_w1h);
    cudaGetSymbolAddress((void**)&w1l, g_w1l);
    cudaGetSymbolAddress((void**)&w2h, g_w2h);
    cudaGetSymbolAddress((void**)&w2l, g_w2l);
    cudaGetSymbolAddress((void**)&ker_buf, g_ker);

    cudaFuncSetAttribute(gemm_split_kernel<1>,
                         cudaFuncAttributeMaxDynamicSharedMemorySize, SMEM_TOT);
    cudaFuncSetAttribute(gemm_split_kernel<2>,
                         cudaFuncAttributeMaxDynamicSharedMemorySize, SMEM_TOT);

    // 0) pre-split inputs to fp16 hi/lo
    {
        int n4 = Bc * Cc * HW / 4;
        split_kernel<<<(n4 + 255) / 256, 256>>>((const float4*)x,
                                                (uint2*)xh, (uint2*)xl, n4);
    }
    {
        int n4 = TNUM * Cc / 4;
        split_kernel<<<(n4 + 255) / 256, 256>>>((const float4*)reduce_w,
                                                (uint2*)w1h, (uint2*)w1l, n4);
    }
    {
        int n4 = GK * KDIM / 4;
        split_kernel<<<(n4 + 255) / 256, 256>>>((const float4*)span_w,
                                                (uint2*)w2h, (uint2*)w2l, n4);
    }

    // 1) GEMM1: T = BN_PReLU(reduce_w @ x), output split (feeds GEMM2)
    {
        dim3 grid((TNUM + BMg - 1) / BMg, (HW + BNg - 1) / BNg, Bc);
        gemm_split_kernel<1><<<grid, 512, SMEM_TOT>>>(
            w1h, w1l, xh, xl,
            nullptr, th, tl,
            TNUM, HW,
            reduce_b, bn_gamma, bn_beta, bn_mean, bn_var, prelu_a);
    }
    // 2) GEMM2: KER = span_w @ T + span_b (fp32 out)
    {
        dim3 grid((GK + BMg - 1) / BMg, (HW + BNg - 1) / BNg, Bc);
        gemm_split_kernel<2><<<grid, 512, SMEM_TOT>>>(
            w2h, w2l, th, tl,
            ker_buf, nullptr, nullptr,
            GK, HW,
            span_b, nullptr, nullptr, nullptr, nullptr, nullptr);
    }
    // 3) involution aggregation
    {
        dim3 grid(Hc / TH, Gc, Bc);
        involution_kernel<<<grid, 256>>>(x, ker_buf, out);
    }
}

// round 6
// speedup vs baseline: 2.3224x; 1.0478x over previous
#include <cuda_runtime.h>
#include <cuda_fp16.h>
#include <cstdint>

// ---------------------------------------------------------------------------
// Problem constants
// ---------------------------------------------------------------------------
#define Bc    4
#define Cc    256
#define Hc    56
#define Wc    56
#define Gc    16
#define Kc    7
#define TNUM  256
#define HW    (Hc * Wc)          // 3136
#define CG    (Cc / Gc)          // 16
#define KK    (Kc * Kc)          // 49
#define GK    (Gc * KK)          // 784
#define EPSc  1e-5f
#define KDIM  256

// ---------------------------------------------------------------------------
// Scratch (no runtime allocation allowed)
// ---------------------------------------------------------------------------
__device__ __half g_xh[Bc * Cc * HW];
__device__ __half g_xl[Bc * Cc * HW];
__device__ __half g_th[Bc * TNUM * HW];
__device__ __half g_tl[Bc * TNUM * HW];
__device__ __half g_w1h[TNUM * Cc];
__device__ __half g_w1l[TNUM * Cc];
__device__ __half g_w2h[GK * KDIM];
__device__ __half g_w2l[GK * KDIM];
__device__ float  g_ker[Bc * GK * HW];

// ---------------------------------------------------------------------------
// helpers
// ---------------------------------------------------------------------------
__device__ __forceinline__ void split2(float x, float y,
                                       uint32_t& hi, uint32_t& lo) {
    __half hx = __float2half_rn(x);
    __half hy = __float2half_rn(y);
    __half lx = __float2half_rn(x - __half2float(hx));
    __half ly = __float2half_rn(y - __half2float(hy));
    hi = (uint32_t)__half_as_ushort(hx) | ((uint32_t)__half_as_ushort(hy) << 16);
    lo = (uint32_t)__half_as_ushort(lx) | ((uint32_t)__half_as_ushort(ly) << 16);
}

__device__ __forceinline__ uint32_t smem_u32(const void* p) {
    uint32_t a;
    asm("{ .reg .u64 t; cvta.to.shared.u64 t, %1; cvt.u32.u64 %0, t; }"
        : "=r"(a) : "l"(p));
    return a;
}

#define MMA16816(Cr, Ar, B0, B1)                                           \
    asm volatile(                                                          \
        "mma.sync.aligned.m16n8k16.row.col.f32.f16.f16.f32 "              \
        "{%0,%1,%2,%3}, {%4,%5,%6,%7}, {%8,%9}, {%0,%1,%2,%3};"           \
        : "+f"((Cr)[0]), "+f"((Cr)[1]), "+f"((Cr)[2]), "+f"((Cr)[3])       \
        : "r"((Ar)[0]), "r"((Ar)[1]), "r"((Ar)[2]), "r"((Ar)[3]),          \
          "r"(B0), "r"(B1))

#define LDSM4(R, addr)                                                     \
    asm volatile("ldmatrix.sync.aligned.m8n8.x4.shared.b16 "               \
        "{%0,%1,%2,%3}, [%4];"                                             \
        : "=r"((R)[0]), "=r"((R)[1]), "=r"((R)[2]), "=r"((R)[3])           \
        : "r"(addr))

#define LDSM4T(R, addr)                                                    \
    asm volatile("ldmatrix.sync.aligned.m8n8.x4.trans.shared.b16 "         \
        "{%0,%1,%2,%3}, [%4];"                                             \
        : "=r"((R)[0]), "=r"((R)[1]), "=r"((R)[2]), "=r"((R)[3])           \
        : "r"(addr))

#define CP_ASYNC16(dst, src, sz)                                           \
    asm volatile("cp.async.cg.shared.global [%0], [%1], 16, %2;"           \
        :: "r"(dst), "l"(src), "r"(sz))
#define CP_COMMIT() asm volatile("cp.async.commit_group;")

// ---------------------------------------------------------------------------
// fp32 -> fp16 hi/lo split (elementwise, float4-vectorized)
// ---------------------------------------------------------------------------
__global__ __launch_bounds__(256)
void split_kernel(const float4* __restrict__ src,
                  uint2* __restrict__ hi, uint2* __restrict__ lo, int n4)
{
    int i = blockIdx.x * blockDim.x + threadIdx.x;
    if (i >= n4) return;
    float4 v = src[i];
    uint32_t h0, l0, h1, l1;
    split2(v.x, v.y, h0, l0);
    split2(v.z, v.w, h1, l1);
    hi[i] = make_uint2(h0, h1);
    lo[i] = make_uint2(l0, l1);
}

// ---------------------------------------------------------------------------
// Split-fp16 HMMA GEMM, cp.async + ldmatrix, 2 CTAs/SM.
//   D[M,N] = A[M,K]*B[K,N], K=256.  3 MMAs per k-step (hh+hl+lh).
// Block: 256 thr (8 warps, 4Mx2N), tile 128x64, BK=32, 3-stage ring (89 KB).
// N=3136 = 49*64 exact -> no N predication at all.
// EPI=1: BN+PReLU, split output. EPI=2: +bias, fp32 output.
// ---------------------------------------------------------------------------
#define BMg 128
#define BNg 64
#define BKg 32
#define NCH (KDIM / BKg)          // 8
#define NST 3
#define PKA 40                    // A smem pitch (halves)
#define PKB 72                    // B smem pitch (halves)
#define A_BY (BMg * PKA * 2)      // 10240
#define B_BY (BKg * PKB * 2)      // 4608
#define STG_BY (2 * A_BY + 2 * B_BY)   // 29696
#define SMEM_TOT (NST * STG_BY)        // 89088

template <int EPI>
__global__ __launch_bounds__(256, 2)
void gemm_split_kernel(const __half* __restrict__ Ahi,  // [M][K]
                       const __half* __restrict__ Alo,
                       const __half* __restrict__ Bhi,  // [batch][K][N]
                       const __half* __restrict__ Blo,
                       float* __restrict__ Cf,
                       __half* __restrict__ Chi,
                       __half* __restrict__ Clo,
                       int M, int Nfull,
                       const float* __restrict__ bias,
                       const float* __restrict__ gamma,
                       const float* __restrict__ beta,
                       const float* __restrict__ mean,
                       const float* __restrict__ var,
                       const float* __restrict__ prelu_a)
{
    extern __shared__ __align__(16) char smem[];
    const uint32_t sbase = smem_u32(smem);

    const int tid  = threadIdx.x;
    const int lane = tid & 31;
    const int wid  = tid >> 5;
    const int wm   = wid & 3;            // M warp 0..3 (32 rows each)
    const int wn   = wid >> 2;           // N warp 0..1 (32 cols each)
    const int lane15 = lane & 15;
    const int hi8    = (lane & 16) >> 1; // 0 or 8
    const int g    = lane >> 2;
    const int t2   = (lane & 3) * 2;

    const int rowBase = blockIdx.x * BMg;
    const int colBase = blockIdx.y * BNg;
    const int batch   = blockIdx.z;
    const __half* BhiP = Bhi + (size_t)batch * KDIM * Nfull;
    const __half* BloP = Blo + (size_t)batch * KDIM * Nfull;

    // cp.async indices
    // A: 128 rows x 64B (4 chunks of 16B) = 512 chunks; 2 per thread
    const int a_idx0 = tid;              // chunk 0
    const int a_idx1 = tid + 256;        // chunk 1
    // B: 32 rows x 128B (8 chunks) = 256 chunks; 1 per thread
    const int b_kr = tid >> 3;           // 0..31
    const int b_nq = tid & 7;            // 16B chunk along n

    auto issue = [&](int ch, int s) {
        const int kc = ch * BKg;
        const uint32_t stg = sbase + s * STG_BY;
#pragma unroll
        for (int i = 0; i < 2; i++) {
            const int idx = i ? a_idx1 : a_idx0;
            const int row = idx >> 2;
            const int kq  = idx & 3;
            const int gm  = rowBase + row;
            const uint32_t sz = (gm < M) ? 16u : 0u;
            const int gmc = (gm < M) ? gm : 0;
            const uint32_t adst = stg + row * (PKA * 2) + kq * 16;
            const size_t  asrc = (size_t)gmc * KDIM + kc + kq * 8;
            CP_ASYNC16(adst,        Ahi + asrc, sz);
            CP_ASYNC16(adst + A_BY, Alo + asrc, sz);
        }
        const uint32_t bdst = stg + 2 * A_BY + b_kr * (PKB * 2) + b_nq * 16;
        const size_t  bsrc = (size_t)(kc + b_kr) * Nfull + colBase + b_nq * 8;
        CP_ASYNC16(bdst,        BhiP + bsrc, 16u);
        CP_ASYNC16(bdst + B_BY, BloP + bsrc, 16u);
        CP_COMMIT();
    };

    float acc[2][4][4];
#pragma unroll
    for (int mt = 0; mt < 2; mt++)
#pragma unroll
        for (int nt = 0; nt < 4; nt++)
#pragma unroll
            for (int i = 0; i < 4; i++) acc[mt][nt][i] = 0.f;

    issue(0, 0); issue(1, 1); issue(2, 2);

    for (int c = 0; c < NCH; c++) {
        if (c <= NCH - 3)      asm volatile("cp.async.wait_group 2;");
        else if (c == NCH - 2) asm volatile("cp.async.wait_group 1;");
        else                   asm volatile("cp.async.wait_group 0;");
        __syncthreads();

        const int s = c % NST;
        const uint32_t aHiB = sbase + s * STG_BY;
        const uint32_t aLoB = aHiB + A_BY;
        const uint32_t bHiB = aHiB + 2 * A_BY;
        const uint32_t bLoB = bHiB + B_BY;

#pragma unroll
        for (int ks = 0; ks < 2; ks++) {
            const int k0 = ks * 16;
            uint32_t ah[2][4], al[2][4], bh[2][4], bl[2][4];
#pragma unroll
            for (int mt = 0; mt < 2; mt++) {
                int row = wm * 32 + mt * 16 + lane15;
                uint32_t off = row * (PKA * 2) + (k0 + hi8) * 2;
                LDSM4(ah[mt], aHiB + off);
                LDSM4(al[mt], aLoB + off);
            }
#pragma unroll
            for (int nb = 0; nb < 2; nb++) {
                int nn   = wn * 32 + nb * 16 + hi8;
                int krow = k0 + lane15;
                uint32_t off = krow * (PKB * 2) + nn * 2;
                LDSM4T(bh[nb], bHiB + off);
                LDSM4T(bl[nb], bLoB + off);
            }
#pragma unroll
            for (int nb = 0; nb < 2; nb++)
#pragma unroll
                for (int ng = 0; ng < 2; ng++) {
                    uint32_t b0h = bh[nb][2 * ng], b1h = bh[nb][2 * ng + 1];
                    uint32_t b0l = bl[nb][2 * ng], b1l = bl[nb][2 * ng + 1];
#pragma unroll
                    for (int mt = 0; mt < 2; mt++) {
                        float* C = acc[mt][nb * 2 + ng];
                        MMA16816(C, ah[mt], b0h, b1h);   // hi*hi
                        MMA16816(C, ah[mt], b0l, b1l);   // hi*lo
                        MMA16816(C, al[mt], b0h, b1h);   // lo*hi
                    }
                }
        }
        __syncthreads();
        if (c + 3 < NCH) issue(c + 3, (c + 3) % NST);
    }

    // ---- epilogue (N always in-bounds: 3136 % 64 == 0) ----
#pragma unroll
    for (int mt = 0; mt < 2; mt++) {
        int r0 = rowBase + wm * 32 + mt * 16 + g;
#pragma unroll
        for (int half_ = 0; half_ < 2; half_++) {
            int rr = r0 + half_ * 8;
            if (rr >= M) continue;
            float bb = bias[rr];
            float sc = 0.f, mn = 0.f, bt = 0.f, aa = 0.f;
            if (EPI == 1) {
                sc = gamma[rr] * rsqrtf(var[rr] + EPSc);
                mn = mean[rr];
                bt = beta[rr];
                aa = prelu_a[0];
            }
#pragma unroll
            for (int nt = 0; nt < 4; nt++) {
                int col = colBase + wn * 32 + nt * 8 + t2;
                float v0 = acc[mt][nt][half_ * 2 + 0] + bb;
                float v1 = acc[mt][nt][half_ * 2 + 1] + bb;
                if (EPI == 1) {
                    v0 = (v0 - mn) * sc + bt;
                    v1 = (v1 - mn) * sc + bt;
                    v0 = v0 > 0.f ? v0 : aa * v0;
                    v1 = v1 > 0.f ? v1 : aa * v1;
                    uint32_t hw_, lw_;
                    split2(v0, v1, hw_, lw_);
                    size_t idx = ((size_t)batch * M + rr) * Nfull + col;
                    *(uint32_t*)(Chi + idx) = hw_;
                    *(uint32_t*)(Clo + idx) = lw_;
                } else {
                    size_t idx = ((size_t)batch * M + rr) * Nfull + col;
                    *(float2*)(Cf + idx) = make_float2(v0, v1);
                }
            }
        }
    }
}

// ---------------------------------------------------------------------------
// Involution aggregation (unchanged)
// ---------------------------------------------------------------------------
#define TH 4

__global__ __launch_bounds__(256)
void involution_kernel(const float* __restrict__ x,
                       const float* __restrict__ ker,
                       float* __restrict__ out)
{
    __shared__ float xs[TH + 6][64];

    const int tileRow = blockIdx.x;
    const int g = blockIdx.y;
    const int b = blockIdx.z;
    const int tid = threadIdx.x;

    const int h0 = tileRow * TH;
    const bool active = tid < TH * Wc;
    const int r  = tid / Wc;
    const int cw = tid % Wc;
    const int h  = h0 + r;

    float kreg[KK];
    if (active) {
        const float* kp = ker + (((size_t)b * GK + g * KK) * HW) + h * Wc + cw;
#pragma unroll
        for (int idx = 0; idx < KK; idx++) kreg[idx] = kp[(size_t)idx * HW];
    }

    for (int ci = 0; ci < CG; ci++) {
        const int c = g * CG + ci;
        const float* xc = x + ((size_t)(b * Cc + c)) * HW;
        for (int i = tid; i < (TH + 6) * 62; i += 256) {
            int rr = i / 62;
            int cc = i % 62;
            int gh = h0 - 3 + rr;
            int gw = cc - 3;
            float v = 0.f;
            if (gh >= 0 && gh < Hc && gw >= 0 && gw < Wc)
                v = xc[gh * Wc + gw];
            xs[rr][cc] = v;
        }
        __syncthreads();
        if (active) {
            float a = 0.f;
#pragma unroll
            for (int i = 0; i < Kc; i++)
#pragma unroll
                for (int j = 0; j < Kc; j++)
                    a += xs[r + i][cw + j] * kreg[i * Kc + j];
            out[((size_t)(b * Cc + c) * Hc + h) * Wc + cw] = a;
        }
        __syncthreads();
    }
}

// ---------------------------------------------------------------------------
// Launch
// ---------------------------------------------------------------------------
extern "C" void kernel_launch(void* const* d_in, const int* in_sizes, int n_in,
                              void* d_out, int out_size)
{
    const float* x        = (const float*)d_in[0];
    const float* reduce_w = (const float*)d_in[1];
    const float* reduce_b = (const float*)d_in[2];
    const float* bn_gamma = (const float*)d_in[3];
    const float* bn_beta  = (const float*)d_in[4];
    const float* bn_mean  = (const float*)d_in[5];
    const float* bn_var   = (const float*)d_in[6];
    const float* prelu_a  = (const float*)d_in[7];
    const float* span_w   = (const float*)d_in[8];
    const float* span_b   = (const float*)d_in[9];
    float* out = (float*)d_out;

    __half *xh, *xl, *th, *tl, *w1h, *w1l, *w2h, *w2l;
    float* ker_buf;
    cudaGetSymbolAddress((void**)&xh, g_xh);
    cudaGetSymbolAddress((void**)&xl, g_xl);
    cudaGetSymbolAddress((void**)&th, g_th);
    cudaGetSymbolAddress((void**)&tl, g_tl);
    cudaGetSymbolAddress((void**)&w1h, g_w1h);
    cudaGetSymbolAddress((void**)&w1l, g_w1l);
    cudaGetSymbolAddress((void**)&w2h, g_w2h);
    cudaGetSymbolAddress((void**)&w2l, g_w2l);
    cudaGetSymbolAddress((void**)&ker_buf, g_ker);

    cudaFuncSetAttribute(gemm_split_kernel<1>,
                         cudaFuncAttributeMaxDynamicSharedMemorySize, SMEM_TOT);
    cudaFuncSetAttribute(gemm_split_kernel<2>,
                         cudaFuncAttributeMaxDynamicSharedMemorySize, SMEM_TOT);

    // 0) pre-split inputs
    {
        int n4 = Bc * Cc * HW / 4;
        split_kernel<<<(n4 + 255) / 256, 256>>>((const float4*)x,
                                                (uint2*)xh, (uint2*)xl, n4);
    }
    {
        int n4 = TNUM * Cc / 4;
        split_kernel<<<(n4 + 255) / 256, 256>>>((const float4*)reduce_w,
                                                (uint2*)w1h, (uint2*)w1l, n4);
    }
    {
        int n4 = GK * KDIM / 4;
        split_kernel<<<(n4 + 255) / 256, 256>>>((const float4*)span_w,
                                                (uint2*)w2h, (uint2*)w2l, n4);
    }

    // 1) GEMM1: T = BN_PReLU(reduce_w @ x), split output (feeds GEMM2)
    {
        dim3 grid(TNUM / BMg, HW / BNg, Bc);           // 2 x 49 x 4
        gemm_split_kernel<1><<<grid, 256, SMEM_TOT>>>(
            w1h, w1l, xh, xl,
            nullptr, th, tl,
            TNUM, HW,
            reduce_b, bn_gamma, bn_beta, bn_mean, bn_var, prelu_a);
    }
    // 2) GEMM2: KER = span_w @ T + span_b (fp32 out)
    {
        dim3 grid((GK + BMg - 1) / BMg, HW / BNg, Bc); // 7 x 49 x 4
        gemm_split_kernel<2><<<grid, 256, SMEM_TOT>>>(
            w2h, w2l, th, tl,
            ker_buf, nullptr, nullptr,
            GK, HW,
            span_b, nullptr, nullptr, nullptr, nullptr, nullptr);
    }
    // 3) involution aggregation
    {
        dim3 grid(Hc / TH, Gc, Bc);
        involution_kernel<<<grid, 256>>>(x, ker_buf, out);
    }
}

// round 7
// speedup vs baseline: 2.7077x; 1.1659x over previous
#include <cuda_runtime.h>
#include <cuda_fp16.h>
#include <cstdint>

// ---------------------------------------------------------------------------
// Problem constants
// ---------------------------------------------------------------------------
#define Bc    4
#define Cc    256
#define Hc    56
#define Wc    56
#define Gc    16
#define Kc    7
#define TNUM  256
#define HW    (Hc * Wc)          // 3136
#define CG    (Cc / Gc)          // 16
#define KK    (Kc * Kc)          // 49
#define GK    (Gc * KK)          // 784
#define EPSc  1e-5f
#define KDIM  256

// ---------------------------------------------------------------------------
// Scratch (no runtime allocation allowed)
// ---------------------------------------------------------------------------
__device__ __half g_xh[Bc * Cc * HW];
__device__ __half g_xl[Bc * Cc * HW];
__device__ __half g_th[Bc * TNUM * HW];
__device__ __half g_tl[Bc * TNUM * HW];
__device__ __half g_w1h[TNUM * Cc];
__device__ __half g_w1l[TNUM * Cc];
__device__ __half g_w2h[GK * KDIM];
__device__ __half g_w2l[GK * KDIM];
__device__ float  g_ker[Bc * GK * HW];

// ---------------------------------------------------------------------------
// helpers
// ---------------------------------------------------------------------------
__device__ __forceinline__ void split2(float x, float y,
                                       uint32_t& hi, uint32_t& lo) {
    __half hx = __float2half_rn(x);
    __half hy = __float2half_rn(y);
    __half lx = __float2half_rn(x - __half2float(hx));
    __half ly = __float2half_rn(y - __half2float(hy));
    hi = (uint32_t)__half_as_ushort(hx) | ((uint32_t)__half_as_ushort(hy) << 16);
    lo = (uint32_t)__half_as_ushort(lx) | ((uint32_t)__half_as_ushort(ly) << 16);
}

__device__ __forceinline__ uint32_t smem_u32(const void* p) {
    uint32_t a;
    asm("{ .reg .u64 t; cvta.to.shared.u64 t, %1; cvt.u32.u64 %0, t; }"
        : "=r"(a) : "l"(p));
    return a;
}

#define MMA16816(Cr, Ar, B0, B1)                                           \
    asm volatile(                                                          \
        "mma.sync.aligned.m16n8k16.row.col.f32.f16.f16.f32 "              \
        "{%0,%1,%2,%3}, {%4,%5,%6,%7}, {%8,%9}, {%0,%1,%2,%3};"           \
        : "+f"((Cr)[0]), "+f"((Cr)[1]), "+f"((Cr)[2]), "+f"((Cr)[3])       \
        : "r"((Ar)[0]), "r"((Ar)[1]), "r"((Ar)[2]), "r"((Ar)[3]),          \
          "r"(B0), "r"(B1))

#define LDSM4(R, addr)                                                     \
    asm volatile("ldmatrix.sync.aligned.m8n8.x4.shared.b16 "               \
        "{%0,%1,%2,%3}, [%4];"                                             \
        : "=r"((R)[0]), "=r"((R)[1]), "=r"((R)[2]), "=r"((R)[3])           \
        : "r"(addr))

#define LDSM4T(R, addr)                                                    \
    asm volatile("ldmatrix.sync.aligned.m8n8.x4.trans.shared.b16 "         \
        "{%0,%1,%2,%3}, [%4];"                                             \
        : "=r"((R)[0]), "=r"((R)[1]), "=r"((R)[2]), "=r"((R)[3])           \
        : "r"(addr))

#define CP_ASYNC16(dst, src, sz)                                           \
    asm volatile("cp.async.cg.shared.global [%0], [%1], 16, %2;"           \
        :: "r"(dst), "l"(src), "r"(sz))
#define CP_COMMIT() asm volatile("cp.async.commit_group;")

// ---------------------------------------------------------------------------
// fp32 -> fp16 hi/lo split (elementwise, float4-vectorized)
// ---------------------------------------------------------------------------
__global__ __launch_bounds__(256)
void split_kernel(const float4* __restrict__ src,
                  uint2* __restrict__ hi, uint2* __restrict__ lo, int n4)
{
    int i = blockIdx.x * blockDim.x + threadIdx.x;
    if (i >= n4) return;
    float4 v = src[i];
    uint32_t h0, l0, h1, l1;
    split2(v.x, v.y, h0, l0);
    split2(v.z, v.w, h1, l1);
    hi[i] = make_uint2(h0, h1);
    lo[i] = make_uint2(l0, l1);
}

// ---------------------------------------------------------------------------
// Split-fp16 HMMA GEMM, cp.async + ldmatrix, 2 CTAs/SM, ONE barrier/chunk.
//   D[M,N] = A[M,K]*B[K,N], K=256.  3 MMAs per k-step (hh+hl+lh).
// Block: 256 thr (8 warps, 4Mx2N), tile 128x64, BK=32, 3-stage ring (89 KB).
// Mainloop: prologue fills 2 stages; each iter: wait(1) -> sync ->
//   issue chunk c+2 into the stage freed last iter -> compute chunk c.
// ---------------------------------------------------------------------------
#define BMg 128
#define BNg 64
#define BKg 32
#define NCH (KDIM / BKg)          // 8
#define NST 3
#define PKA 40                    // A smem pitch (halves)
#define PKB 72                    // B smem pitch (halves)
#define A_BY (BMg * PKA * 2)      // 10240
#define B_BY (BKg * PKB * 2)      // 4608
#define STG_BY (2 * A_BY + 2 * B_BY)   // 29696
#define SMEM_TOT (NST * STG_BY)        // 89088

template <int EPI>
__global__ __launch_bounds__(256, 2)
void gemm_split_kernel(const __half* __restrict__ Ahi,  // [M][K]
                       const __half* __restrict__ Alo,
                       const __half* __restrict__ Bhi,  // [batch][K][N]
                       const __half* __restrict__ Blo,
                       float* __restrict__ Cf,
                       __half* __restrict__ Chi,
                       __half* __restrict__ Clo,
                       int M, int Nfull,
                       const float* __restrict__ bias,
                       const float* __restrict__ gamma,
                       const float* __restrict__ beta,
                       const float* __restrict__ mean,
                       const float* __restrict__ var,
                       const float* __restrict__ prelu_a)
{
    extern __shared__ __align__(16) char smem[];
    const uint32_t sbase = smem_u32(smem);

    const int tid  = threadIdx.x;
    const int lane = tid & 31;
    const int wid  = tid >> 5;
    const int wm   = wid & 3;            // M warp 0..3 (32 rows each)
    const int wn   = wid >> 2;           // N warp 0..1 (32 cols each)
    const int lane15 = lane & 15;
    const int hi8    = (lane & 16) >> 1; // 0 or 8
    const int g    = lane >> 2;
    const int t2   = (lane & 3) * 2;

    const int rowBase = blockIdx.x * BMg;
    const int colBase = blockIdx.y * BNg;
    const int batch   = blockIdx.z;
    const __half* BhiP = Bhi + (size_t)batch * KDIM * Nfull;
    const __half* BloP = Blo + (size_t)batch * KDIM * Nfull;

    // cp.async indices
    const int a_idx0 = tid;              // A chunk 0 of 2
    const int a_idx1 = tid + 256;        // A chunk 1 of 2
    const int b_kr = tid >> 3;           // 0..31
    const int b_nq = tid & 7;            // 16B chunk along n

    auto issue = [&](int ch, int s) {
        const int kc = ch * BKg;
        const uint32_t stg = sbase + s * STG_BY;
#pragma unroll
        for (int i = 0; i < 2; i++) {
            const int idx = i ? a_idx1 : a_idx0;
            const int row = idx >> 2;
            const int kq  = idx & 3;
            const int gm  = rowBase + row;
            const uint32_t sz = (gm < M) ? 16u : 0u;
            const int gmc = (gm < M) ? gm : 0;
            const uint32_t adst = stg + row * (PKA * 2) + kq * 16;
            const size_t  asrc = (size_t)gmc * KDIM + kc + kq * 8;
            CP_ASYNC16(adst,        Ahi + asrc, sz);
            CP_ASYNC16(adst + A_BY, Alo + asrc, sz);
        }
        const uint32_t bdst = stg + 2 * A_BY + b_kr * (PKB * 2) + b_nq * 16;
        const size_t  bsrc = (size_t)(kc + b_kr) * Nfull + colBase + b_nq * 8;
        CP_ASYNC16(bdst,        BhiP + bsrc, 16u);
        CP_ASYNC16(bdst + B_BY, BloP + bsrc, 16u);
        CP_COMMIT();
    };

    float acc[2][4][4];
#pragma unroll
    for (int mt = 0; mt < 2; mt++)
#pragma unroll
        for (int nt = 0; nt < 4; nt++)
#pragma unroll
            for (int i = 0; i < 4; i++) acc[mt][nt][i] = 0.f;

    // prologue: NST-1 = 2 chunks in flight
    issue(0, 0); issue(1, 1);

    for (int c = 0; c < NCH; c++) {
        if (c < NCH - 1) asm volatile("cp.async.wait_group 1;");
        else             asm volatile("cp.async.wait_group 0;");
        __syncthreads();                       // stage c ready; prev compute drained
        if (c + 2 < NCH) issue(c + 2, (c + 2) % NST);  // stage freed last iter

        const int s = c % NST;
        const uint32_t aHiB = sbase + s * STG_BY;
        const uint32_t aLoB = aHiB + A_BY;
        const uint32_t bHiB = aHiB + 2 * A_BY;
        const uint32_t bLoB = bHiB + B_BY;

#pragma unroll
        for (int ks = 0; ks < 2; ks++) {
            const int k0 = ks * 16;
            uint32_t ah[2][4], al[2][4], bh[2][4], bl[2][4];
#pragma unroll
            for (int mt = 0; mt < 2; mt++) {
                int row = wm * 32 + mt * 16 + lane15;
                uint32_t off = row * (PKA * 2) + (k0 + hi8) * 2;
                LDSM4(ah[mt], aHiB + off);
                LDSM4(al[mt], aLoB + off);
            }
#pragma unroll
            for (int nb = 0; nb < 2; nb++) {
                int nn   = wn * 32 + nb * 16 + hi8;
                int krow = k0 + lane15;
                uint32_t off = krow * (PKB * 2) + nn * 2;
                LDSM4T(bh[nb], bHiB + off);
                LDSM4T(bl[nb], bLoB + off);
            }
#pragma unroll
            for (int nb = 0; nb < 2; nb++)
#pragma unroll
                for (int ng = 0; ng < 2; ng++) {
                    uint32_t b0h = bh[nb][2 * ng], b1h = bh[nb][2 * ng + 1];
                    uint32_t b0l = bl[nb][2 * ng], b1l = bl[nb][2 * ng + 1];
#pragma unroll
                    for (int mt = 0; mt < 2; mt++) {
                        float* C = acc[mt][nb * 2 + ng];
                        MMA16816(C, ah[mt], b0h, b1h);   // hi*hi
                        MMA16816(C, ah[mt], b0l, b1l);   // hi*lo
                        MMA16816(C, al[mt], b0h, b1h);   // lo*hi
                    }
                }
        }
    }

    // ---- epilogue (N always in-bounds: 3136 % 64 == 0) ----
#pragma unroll
    for (int mt = 0; mt < 2; mt++) {
        int r0 = rowBase + wm * 32 + mt * 16 + g;
#pragma unroll
        for (int half_ = 0; half_ < 2; half_++) {
            int rr = r0 + half_ * 8;
            if (rr >= M) continue;
            float bb = bias[rr];
            float sc = 0.f, mn = 0.f, bt = 0.f, aa = 0.f;
            if (EPI == 1) {
                sc = gamma[rr] * rsqrtf(var[rr] + EPSc);
                mn = mean[rr];
                bt = beta[rr];
                aa = prelu_a[0];
            }
#pragma unroll
            for (int nt = 0; nt < 4; nt++) {
                int col = colBase + wn * 32 + nt * 8 + t2;
                float v0 = acc[mt][nt][half_ * 2 + 0] + bb;
                float v1 = acc[mt][nt][half_ * 2 + 1] + bb;
                if (EPI == 1) {
                    v0 = (v0 - mn) * sc + bt;
                    v1 = (v1 - mn) * sc + bt;
                    v0 = v0 > 0.f ? v0 : aa * v0;
                    v1 = v1 > 0.f ? v1 : aa * v1;
                    uint32_t hw_, lw_;
                    split2(v0, v1, hw_, lw_);
                    size_t idx = ((size_t)batch * M + rr) * Nfull + col;
                    *(uint32_t*)(Chi + idx) = hw_;
                    *(uint32_t*)(Clo + idx) = lw_;
                } else {
                    size_t idx = ((size_t)batch * M + rr) * Nfull + col;
                    *(float2*)(Cf + idx) = make_float2(v0, v1);
                }
            }
        }
    }
}

// ---------------------------------------------------------------------------
// Involution aggregation — ONE barrier per block.
// All 16 channels' halos staged to smem in a single cooperative burst
// (16 x 10 x 62 floats, 40 KB), then each thread sweeps its pixel across
// the group's 16 channels with its 49 ker taps in registers.
// ---------------------------------------------------------------------------
#define TH 4
#define HALO_R (TH + 6)           // 10
#define HALO_C 62
#define HALO_P 64                 // smem pitch

__global__ __launch_bounds__(256)
void involution_kernel(const float* __restrict__ x,
                       const float* __restrict__ ker,
                       float* __restrict__ out)
{
    __shared__ float xs[CG][HALO_R][HALO_P];   // 40 KB

    const int tileRow = blockIdx.x;
    const int g = blockIdx.y;
    const int b = blockIdx.z;
    const int tid = threadIdx.x;

    const int h0 = tileRow * TH;
    const bool active = tid < TH * Wc;          // 224
    const int r  = tid / Wc;
    const int cw = tid % Wc;
    const int h  = h0 + r;

    // ker taps -> registers (coalesced along w), overlapped with halo loads
    float kreg[KK];
    if (active) {
        const float* kp = ker + (((size_t)b * GK + g * KK) * HW) + h * Wc + cw;
#pragma unroll
        for (int idx = 0; idx < KK; idx++) kreg[idx] = kp[(size_t)idx * HW];
    }

    // cooperative halo load: 16 channels x 10 rows x 62 cols
    const float* xg = x + ((size_t)b * Cc + g * CG) * HW;
    for (int i = tid; i < CG * HALO_R * HALO_C; i += 256) {
        int ch  = i / (HALO_R * HALO_C);
        int rem = i - ch * (HALO_R * HALO_C);
        int rr  = rem / HALO_C;
        int cc  = rem - rr * HALO_C;
        int gh  = h0 - 3 + rr;
        int gw  = cc - 3;
        float v = 0.f;
        if (gh >= 0 && gh < Hc && gw >= 0 && gw < Wc)
            v = xg[(size_t)ch * HW + gh * Wc + gw];
        xs[ch][rr][cc] = v;
    }
    __syncthreads();

    if (active) {
        float* op = out + (((size_t)b * Cc + g * CG) * Hc + h) * Wc + cw;
#pragma unroll 4
        for (int ci = 0; ci < CG; ci++) {
            float a = 0.f;
#pragma unroll
            for (int i = 0; i < Kc; i++)
#pragma unroll
                for (int j = 0; j < Kc; j++)
                    a += xs[ci][r + i][cw + j] * kreg[i * Kc + j];
            op[(size_t)ci * HW] = a;
        }
    }
}

// ---------------------------------------------------------------------------
// Launch
// ---------------------------------------------------------------------------
extern "C" void kernel_launch(void* const* d_in, const int* in_sizes, int n_in,
                              void* d_out, int out_size)
{
    const float* x        = (const float*)d_in[0];
    const float* reduce_w = (const float*)d_in[1];
    const float* reduce_b = (const float*)d_in[2];
    const float* bn_gamma = (const float*)d_in[3];
    const float* bn_beta  = (const float*)d_in[4];
    const float* bn_mean  = (const float*)d_in[5];
    const float* bn_var   = (const float*)d_in[6];
    const float* prelu_a  = (const float*)d_in[7];
    const float* span_w   = (const float*)d_in[8];
    const float* span_b   = (const float*)d_in[9];
    float* out = (float*)d_out;

    __half *xh, *xl, *th, *tl, *w1h, *w1l, *w2h, *w2l;
    float* ker_buf;
    cudaGetSymbolAddress((void**)&xh, g_xh);
    cudaGetSymbolAddress((void**)&xl, g_xl);
    cudaGetSymbolAddress((void**)&th, g_th);
    cudaGetSymbolAddress((void**)&tl, g_tl);
    cudaGetSymbolAddress((void**)&w1h, g_w1h);
    cudaGetSymbolAddress((void**)&w1l, g_w1l);
    cudaGetSymbolAddress((void**)&w2h, g_w2h);
    cudaGetSymbolAddress((void**)&w2l, g_w2l);
    cudaGetSymbolAddress((void**)&ker_buf, g_ker);

    cudaFuncSetAttribute(gemm_split_kernel<1>,
                         cudaFuncAttributeMaxDynamicSharedMemorySize, SMEM_TOT);
    cudaFuncSetAttribute(gemm_split_kernel<2>,
                         cudaFuncAttributeMaxDynamicSharedMemorySize, SMEM_TOT);

    // 0) pre-split inputs
    {
        int n4 = Bc * Cc * HW / 4;
        split_kernel<<<(n4 + 255) / 256, 256>>>((const float4*)x,
                                                (uint2*)xh, (uint2*)xl, n4);
    }
    {
        int n4 = TNUM * Cc / 4;
        split_kernel<<<(n4 + 255) / 256, 256>>>((const float4*)reduce_w,
                                                (uint2*)w1h, (uint2*)w1l, n4);
    }
    {
        int n4 = GK * KDIM / 4;
        split_kernel<<<(n4 + 255) / 256, 256>>>((const float4*)span_w,
                                                (uint2*)w2h, (uint2*)w2l, n4);
    }

    // 1) GEMM1: T = BN_PReLU(reduce_w @ x), split output (feeds GEMM2)
    {
        dim3 grid(TNUM / BMg, HW / BNg, Bc);           // 2 x 49 x 4
        gemm_split_kernel<1><<<grid, 256, SMEM_TOT>>>(
            w1h, w1l, xh, xl,
            nullptr, th, tl,
            TNUM, HW,
            reduce_b, bn_gamma, bn_beta, bn_mean, bn_var, prelu_a);
    }
    // 2) GEMM2: KER = span_w @ T + span_b (fp32 out)
    {
        dim3 grid((GK + BMg - 1) / BMg, HW / BNg, Bc); // 7 x 49 x 4
        gemm_split_kernel<2><<<grid, 256, SMEM_TOT>>>(
            w2h, w2l, th, tl,
            ker_buf, nullptr, nullptr,
            GK, HW,
            span_b, nullptr, nullptr, nullptr, nullptr, nullptr);
    }
    // 3) involution aggregation
    {
        dim3 grid(Hc / TH, Gc, Bc);
        involution_kernel<<<grid, 256>>>(x, ker_buf, out);
    }
}